// round 10
// baseline (speedup 1.0000x reference)
#include <cuda_runtime.h>

#define T_STEPS 512

// ---- packed f32x2 helpers (sm_100+ PTX) ----
__device__ __forceinline__ unsigned long long pack2(float lo, float hi){
    unsigned long long r;
    asm("mov.b64 %0, {%1, %2};" : "=l"(r) : "f"(lo), "f"(hi));
    return r;
}
__device__ __forceinline__ void ffma2(unsigned long long& acc, unsigned long long a, unsigned long long b){
    asm("fma.rn.f32x2 %0, %1, %2, %0;" : "+l"(acc) : "l"(a), "l"(b));
}
__device__ __forceinline__ float2 unpack2(unsigned long long v){
    float2 f;
    asm("mov.b64 {%0, %1}, %2;" : "=f"(f.x), "=f"(f.y) : "l"(v));
    return f;
}
// HW tanh (MUFU): 1 op, err ~2^-10.8. sigmoid(x)=0.5*tanh(x/2)+0.5.
__device__ __forceinline__ float tanh_a(float x){
    float r; asm("tanh.approx.f32 %0, %1;" : "=f"(r) : "f"(x)); return r;
}
__device__ __forceinline__ float sigmoid_a(float x){
    return fmaf(0.5f, tanh_a(0.5f * x), 0.5f);
}

// Architecture = R7 optimum: TWO batches per warp, one warp per block,
// grid = B/2 = 1024 -> one wave, ~2 warps/SMSP.
// NEW this round: the step body is STAGGERED per batch --
//   MAC(b0) -> gates(b0) -> MAC(b1) -> gates(b1)
// so batch0's serial gate/MUFU tail issues UNDER batch1's FFMA2 stream
// instead of both tails landing after a joint MAC. One tail hidden per step.
__global__ void __launch_bounds__(32, 8) lstm_stag(
    const float* __restrict__ x,
    const float* __restrict__ W_ih,
    const float* __restrict__ W_hh,
    const float* __restrict__ b_ih,
    const float* __restrict__ b_hh,
    const float* __restrict__ W_fc,
    const float* __restrict__ b_fc,
    float* __restrict__ out,
    int B)
{
    const int lane = threadIdx.x;
    const int b0 = blockIdx.x * 2;
    const int b1 = b0 + 1;
    const bool has1 = (b1 < B);
    const int b1m = has1 ? b1 : b0;

    __shared__ __align__(16) float hs[2][32][36];
    __shared__ float wfcs[32];

    // ---- preload shared weights into registers (amortized over 512 steps) ----
    unsigned long long w2[4][16];   // 4 gate rows x 16 packed k-pairs = 128 regs
    unsigned long long wx2[4];
    float bias[4];
#pragma unroll
    for (int r = 0; r < 4; r++){
        const int row = r * 32 + lane;
        const float4* wr = reinterpret_cast<const float4*>(W_hh) + row * 8;
#pragma unroll
        for (int q = 0; q < 8; q++){
            float4 v = wr[q];
            w2[r][2*q]   = pack2(v.x, v.y);
            w2[r][2*q+1] = pack2(v.z, v.w);
        }
        wx2[r]  = pack2(W_ih[row*2 + 0], W_ih[row*2 + 1]);
        bias[r] = b_ih[row] + b_hh[row];
    }
    wfcs[lane] = W_fc[lane];
    const float bfc = b_fc[0];

    float c0 = 0.0f, c1 = 0.0f;
    hs[0][31][lane] = 0.0f;   // h_{-1} = 0 (read by step 0)
    hs[1][31][lane] = 0.0f;
    __syncwarp();

    const float2* xr0 = reinterpret_cast<const float2*>(x) + (size_t)b0  * T_STEPS;
    const float2* xr1 = reinterpret_cast<const float2*>(x) + (size_t)b1m * T_STEPS;
    float2 xv0 = xr0[0];
    float2 xv1 = xr1[0];

    for (int tb = 0; tb < T_STEPS / 32; tb++){
#pragma unroll 1
        for (int ts = 0; ts < 32; ts++){
            const int t = (tb << 5) + ts;
            const int tn = (t + 1 < T_STEPS) ? (t + 1) : t;
            float2 xn0 = xr0[tn];           // prefetch next inputs
            float2 xn1 = xr1[tn];

            const int rp = (ts + 31) & 31;  // row holding h_{t-1}
            const ulonglong2* hp0 = reinterpret_cast<const ulonglong2*>(&hs[0][rp][0]);
            const ulonglong2* hp1 = reinterpret_cast<const ulonglong2*>(&hs[1][rp][0]);

            // ================= batch 0: MAC =================
            unsigned long long xp0 = pack2(xv0.x, xv0.y);
            unsigned long long a00 = pack2(bias[0], 0.f), a01 = pack2(bias[1], 0.f);
            unsigned long long a02 = pack2(bias[2], 0.f), a03 = pack2(bias[3], 0.f);
            ffma2(a00, xp0, wx2[0]); ffma2(a01, xp0, wx2[1]);
            ffma2(a02, xp0, wx2[2]); ffma2(a03, xp0, wx2[3]);
#pragma unroll
            for (int q = 0; q < 8; q++){
                ulonglong2 v0 = hp0[q];
                ffma2(a00, v0.x, w2[0][2*q]);   ffma2(a01, v0.x, w2[1][2*q]);
                ffma2(a02, v0.x, w2[2][2*q]);   ffma2(a03, v0.x, w2[3][2*q]);
                ffma2(a00, v0.y, w2[0][2*q+1]); ffma2(a01, v0.y, w2[1][2*q+1]);
                ffma2(a02, v0.y, w2[2][2*q+1]); ffma2(a03, v0.y, w2[3][2*q+1]);
            }

            // ====== batch 0: gates (issues under batch 1's MAC below) ======
            {
                float2 f0 = unpack2(a00), f1 = unpack2(a01);
                float2 f2 = unpack2(a02), f3 = unpack2(a03);
                const float ig = sigmoid_a(f0.x + f0.y);
                const float fg = sigmoid_a(f1.x + f1.y);
                const float gg = tanh_a   (f2.x + f2.y);
                const float og = sigmoid_a(f3.x + f3.y);
                c0 = fmaf(fg, c0, ig * gg);
                hs[0][ts][lane] = og * tanh_a(c0);
            }

            // ================= batch 1: MAC =================
            unsigned long long xp1 = pack2(xv1.x, xv1.y);
            unsigned long long a10 = pack2(bias[0], 0.f), a11 = pack2(bias[1], 0.f);
            unsigned long long a12 = pack2(bias[2], 0.f), a13 = pack2(bias[3], 0.f);
            ffma2(a10, xp1, wx2[0]); ffma2(a11, xp1, wx2[1]);
            ffma2(a12, xp1, wx2[2]); ffma2(a13, xp1, wx2[3]);
#pragma unroll
            for (int q = 0; q < 8; q++){
                ulonglong2 v1 = hp1[q];
                ffma2(a10, v1.x, w2[0][2*q]);   ffma2(a11, v1.x, w2[1][2*q]);
                ffma2(a12, v1.x, w2[2][2*q]);   ffma2(a13, v1.x, w2[3][2*q]);
                ffma2(a10, v1.y, w2[0][2*q+1]); ffma2(a11, v1.y, w2[1][2*q+1]);
                ffma2(a12, v1.y, w2[2][2*q+1]); ffma2(a13, v1.y, w2[3][2*q+1]);
            }

            // ================= batch 1: gates =================
            {
                float2 f0 = unpack2(a10), f1 = unpack2(a11);
                float2 f2 = unpack2(a12), f3 = unpack2(a13);
                const float ig = sigmoid_a(f0.x + f0.y);
                const float fg = sigmoid_a(f1.x + f1.y);
                const float gg = tanh_a   (f2.x + f2.y);
                const float og = sigmoid_a(f3.x + f3.y);
                c1 = fmaf(fg, c1, ig * gg);
                hs[1][ts][lane] = og * tanh_a(c1);
            }

            __syncwarp();   // publish h_t before next step reads it
            xv0 = xn0;
            xv1 = xn1;
        }

        // ---- deferred FC head for this 32-step chunk ----
        // lane j computes out[t = tb*32 + j] = dot(h_t, wfc) + bfc
        float p0 = 0.0f, p1 = 0.0f;
#pragma unroll
        for (int k = 0; k < 32; k++){
            const float w = wfcs[k];
            p0 = fmaf(hs[0][lane][k], w, p0);
            p1 = fmaf(hs[1][lane][k], w, p1);
        }
        const int to = (tb << 5) + lane;
        out[(size_t)b0 * T_STEPS + to] = p0 + bfc;
        if (has1) out[(size_t)b1 * T_STEPS + to] = p1 + bfc;
        __syncwarp();   // chunk rows may be overwritten next chunk
    }
}

extern "C" void kernel_launch(void* const* d_in, const int* in_sizes, int n_in,
                              void* d_out, int out_size)
{
    const float* x   = (const float*)d_in[0];
    const float* Wih = (const float*)d_in[1];
    const float* Whh = (const float*)d_in[2];
    const float* bih = (const float*)d_in[3];
    const float* bhh = (const float*)d_in[4];
    const float* Wfc = (const float*)d_in[5];
    const float* bfc = (const float*)d_in[6];
    float* out = (float*)d_out;

    const int B = out_size / T_STEPS;      // OUT=1 -> out_size = B*T
    const int grid = (B + 1) / 2;          // two batch elements per warp
    lstm_stag<<<grid, 32>>>(x, Wih, Whh, bih, bhh, Wfc, bfc, out, B);
}

// round 12
// speedup vs baseline: 1.0608x; 1.0608x over previous
#include <cuda_runtime.h>

#define T_STEPS 512

// ---- packed f32x2 helpers (sm_100+ PTX) ----
__device__ __forceinline__ unsigned long long pack2(float lo, float hi){
    unsigned long long r;
    asm("mov.b64 %0, {%1, %2};" : "=l"(r) : "f"(lo), "f"(hi));
    return r;
}
__device__ __forceinline__ void ffma2(unsigned long long& acc, unsigned long long a, unsigned long long b){
    asm("fma.rn.f32x2 %0, %1, %2, %0;" : "+l"(acc) : "l"(a), "l"(b));
}
__device__ __forceinline__ unsigned long long add2(unsigned long long a, unsigned long long b){
    unsigned long long r;
    asm("add.rn.f32x2 %0, %1, %2;" : "=l"(r) : "l"(a), "l"(b));
    return r;
}
__device__ __forceinline__ float2 unpack2(unsigned long long v){
    float2 f;
    asm("mov.b64 {%0, %1}, %2;" : "=f"(f.x), "=f"(f.y) : "l"(v));
    return f;
}
// HW tanh (MUFU): 1 op, err ~2^-10.8. sigmoid(x)=0.5*tanh(x/2)+0.5.
__device__ __forceinline__ float tanh_a(float x){
    float r; asm("tanh.approx.f32 %0, %1;" : "=f"(r) : "f"(x)); return r;
}
__device__ __forceinline__ float sigmoid_a(float x){
    return fmaf(0.5f, tanh_a(0.5f * x), 0.5f);
}

// Architecture = R7 optimum: TWO batches per warp, one warp per block,
// grid = B/2 = 1024 -> one wave, ~2 warps/SMSP. Joint MAC (8->16 chains).
// NEW:
//  (1) ANTI-PHASE: odd blocks burn a one-time ~500-cyc dependent MUFU chain
//      before the step loop (result * 0.0f -> exact no-op on output), so the
//      two co-SMSP warps alternate MAC phase (FMA-bound) with tail phase
//      (MUFU/LSU-bound) instead of colliding in both.
//  (2) SPLIT-K accumulators: 2 per gate per batch (merged by one packed add),
//      halving FFMA2 chain depth (16->8) -> MAC issue is pure-throughput-bound.
__global__ void __launch_bounds__(32, 8) lstm_ap(
    const float* __restrict__ x,
    const float* __restrict__ W_ih,
    const float* __restrict__ W_hh,
    const float* __restrict__ b_ih,
    const float* __restrict__ b_hh,
    const float* __restrict__ W_fc,
    const float* __restrict__ b_fc,
    float* __restrict__ out,
    int B)
{
    const int lane = threadIdx.x;
    const int b0 = blockIdx.x * 2;
    const int b1 = b0 + 1;
    const bool has1 = (b1 < B);
    const int b1m = has1 ? b1 : b0;

    __shared__ __align__(16) float hs[2][32][36];
    __shared__ float wfcs[32];

    // ---- preload shared weights into registers (amortized over 512 steps) ----
    unsigned long long w2[4][16];   // 4 gate rows x 16 packed k-pairs = 128 regs
    unsigned long long wx2[4];
    float bias[4];
#pragma unroll
    for (int r = 0; r < 4; r++){
        const int row = r * 32 + lane;
        const float4* wr = reinterpret_cast<const float4*>(W_hh) + row * 8;
#pragma unroll
        for (int q = 0; q < 8; q++){
            float4 v = wr[q];
            w2[r][2*q]   = pack2(v.x, v.y);
            w2[r][2*q+1] = pack2(v.z, v.w);
        }
        wx2[r]  = pack2(W_ih[row*2 + 0], W_ih[row*2 + 1]);
        bias[r] = b_ih[row] + b_hh[row];
    }
    wfcs[lane] = W_fc[lane];
    const float bfc = b_fc[0];

    // ---- one-time anti-phase delay for odd blocks (~32 x lat16 MUFU) ----
    // d stays finite (tanh-bounded), d * 0.0f == 0.0f exactly -> no output effect.
    float c0 = 0.0f, c1 = 0.0f;
    if (blockIdx.x & 1){
        float d = bias[0] + 1.0f;
#pragma unroll
        for (int i = 0; i < 32; i++)
            d = tanh_a(d + 0.7f);
        c0 = d * 0.0f;   // == 0.0f (d finite); keeps the chain alive
    }

    hs[0][31][lane] = 0.0f;   // h_{-1} = 0 (read by step 0)
    hs[1][31][lane] = 0.0f;
    __syncwarp();

    const float2* xr0 = reinterpret_cast<const float2*>(x) + (size_t)b0  * T_STEPS;
    const float2* xr1 = reinterpret_cast<const float2*>(x) + (size_t)b1m * T_STEPS;
    float2 xv0 = xr0[0];
    float2 xv1 = xr1[0];

    for (int tb = 0; tb < T_STEPS / 32; tb++){
#pragma unroll 1
        for (int ts = 0; ts < 32; ts++){
            const int t = (tb << 5) + ts;
            const int tn = (t + 1 < T_STEPS) ? (t + 1) : t;
            float2 xn0 = xr0[tn];           // prefetch next inputs
            float2 xn1 = xr1[tn];

            const int rp = (ts + 31) & 31;  // row holding h_{t-1}
            const ulonglong2* hp0 = reinterpret_cast<const ulonglong2*>(&hs[0][rp][0]);
            const ulonglong2* hp1 = reinterpret_cast<const ulonglong2*>(&hs[1][rp][0]);

            // primary accumulators carry bias + x-projection
            unsigned long long xp0 = pack2(xv0.x, xv0.y);
            unsigned long long xp1 = pack2(xv1.x, xv1.y);
            unsigned long long a00 = pack2(bias[0], 0.f), a01 = pack2(bias[1], 0.f);
            unsigned long long a02 = pack2(bias[2], 0.f), a03 = pack2(bias[3], 0.f);
            unsigned long long a10 = a00, a11 = a01, a12 = a02, a13 = a03;
            ffma2(a00, xp0, wx2[0]); ffma2(a01, xp0, wx2[1]);
            ffma2(a02, xp0, wx2[2]); ffma2(a03, xp0, wx2[3]);
            ffma2(a10, xp1, wx2[0]); ffma2(a11, xp1, wx2[1]);
            ffma2(a12, xp1, wx2[2]); ffma2(a13, xp1, wx2[3]);
            // secondary (split-k) accumulators
            unsigned long long s00 = 0ull, s01 = 0ull, s02 = 0ull, s03 = 0ull;
            unsigned long long s10 = 0ull, s11 = 0ull, s12 = 0ull, s13 = 0ull;

            // MAC core: 128 packed FFMA2 across 16 independent chains (depth 8)
#pragma unroll
            for (int q = 0; q < 4; q++){
                ulonglong2 v0 = hp0[q];
                ulonglong2 v1 = hp1[q];
                ffma2(a00, v0.x, w2[0][2*q]);   ffma2(a01, v0.x, w2[1][2*q]);
                ffma2(a02, v0.x, w2[2][2*q]);   ffma2(a03, v0.x, w2[3][2*q]);
                ffma2(a10, v1.x, w2[0][2*q]);   ffma2(a11, v1.x, w2[1][2*q]);
                ffma2(a12, v1.x, w2[2][2*q]);   ffma2(a13, v1.x, w2[3][2*q]);
                ffma2(a00, v0.y, w2[0][2*q+1]); ffma2(a01, v0.y, w2[1][2*q+1]);
                ffma2(a02, v0.y, w2[2][2*q+1]); ffma2(a03, v0.y, w2[3][2*q+1]);
                ffma2(a10, v1.y, w2[0][2*q+1]); ffma2(a11, v1.y, w2[1][2*q+1]);
                ffma2(a12, v1.y, w2[2][2*q+1]); ffma2(a13, v1.y, w2[3][2*q+1]);
            }
#pragma unroll
            for (int q = 4; q < 8; q++){
                ulonglong2 v0 = hp0[q];
                ulonglong2 v1 = hp1[q];
                ffma2(s00, v0.x, w2[0][2*q]);   ffma2(s01, v0.x, w2[1][2*q]);
                ffma2(s02, v0.x, w2[2][2*q]);   ffma2(s03, v0.x, w2[3][2*q]);
                ffma2(s10, v1.x, w2[0][2*q]);   ffma2(s11, v1.x, w2[1][2*q]);
                ffma2(s12, v1.x, w2[2][2*q]);   ffma2(s13, v1.x, w2[3][2*q]);
                ffma2(s00, v0.y, w2[0][2*q+1]); ffma2(s01, v0.y, w2[1][2*q+1]);
                ffma2(s02, v0.y, w2[2][2*q+1]); ffma2(s03, v0.y, w2[3][2*q+1]);
                ffma2(s10, v1.y, w2[0][2*q+1]); ffma2(s11, v1.y, w2[1][2*q+1]);
                ffma2(s12, v1.y, w2[2][2*q+1]); ffma2(s13, v1.y, w2[3][2*q+1]);
            }

            // gates, batch 0
            {
                float2 f0 = unpack2(add2(a00, s00)), f1 = unpack2(add2(a01, s01));
                float2 f2 = unpack2(add2(a02, s02)), f3 = unpack2(add2(a03, s03));
                const float ig = sigmoid_a(f0.x + f0.y);
                const float fg = sigmoid_a(f1.x + f1.y);
                const float gg = tanh_a   (f2.x + f2.y);
                const float og = sigmoid_a(f3.x + f3.y);
                c0 = fmaf(fg, c0, ig * gg);
                hs[0][ts][lane] = og * tanh_a(c0);
            }
            // gates, batch 1
            {
                float2 f0 = unpack2(add2(a10, s10)), f1 = unpack2(add2(a11, s11));
                float2 f2 = unpack2(add2(a12, s12)), f3 = unpack2(add2(a13, s13));
                const float ig = sigmoid_a(f0.x + f0.y);
                const float fg = sigmoid_a(f1.x + f1.y);
                const float gg = tanh_a   (f2.x + f2.y);
                const float og = sigmoid_a(f3.x + f3.y);
                c1 = fmaf(fg, c1, ig * gg);
                hs[1][ts][lane] = og * tanh_a(c1);
            }

            __syncwarp();   // publish h_t before next step reads it
            xv0 = xn0;
            xv1 = xn1;
        }

        // ---- deferred FC head for this 32-step chunk ----
        // lane j computes out[t = tb*32 + j] = dot(h_t, wfc) + bfc
        float p0 = 0.0f, p1 = 0.0f;
#pragma unroll
        for (int k = 0; k < 32; k++){
            const float w = wfcs[k];
            p0 = fmaf(hs[0][lane][k], w, p0);
            p1 = fmaf(hs[1][lane][k], w, p1);
        }
        const int to = (tb << 5) + lane;
        out[(size_t)b0 * T_STEPS + to] = p0 + bfc;
        if (has1) out[(size_t)b1 * T_STEPS + to] = p1 + bfc;
        __syncwarp();   // chunk rows may be overwritten next chunk
    }
}

extern "C" void kernel_launch(void* const* d_in, const int* in_sizes, int n_in,
                              void* d_out, int out_size)
{
    const float* x   = (const float*)d_in[0];
    const float* Wih = (const float*)d_in[1];
    const float* Whh = (const float*)d_in[2];
    const float* bih = (const float*)d_in[3];
    const float* bhh = (const float*)d_in[4];
    const float* Wfc = (const float*)d_in[5];
    const float* bfc = (const float*)d_in[6];
    float* out = (float*)d_out;

    const int B = out_size / T_STEPS;      // OUT=1 -> out_size = B*T
    const int grid = (B + 1) / 2;          // two batch elements per warp
    lstm_ap<<<grid, 32>>>(x, Wih, Whh, bih, bhh, Wfc, bfc, out, B);
}

// round 14
// speedup vs baseline: 1.0961x; 1.0333x over previous
#include <cuda_runtime.h>

#define T_STEPS 512

// ---- packed f32x2 helpers (sm_100+ PTX) ----
__device__ __forceinline__ unsigned long long pack2(float lo, float hi){
    unsigned long long r;
    asm("mov.b64 %0, {%1, %2};" : "=l"(r) : "f"(lo), "f"(hi));
    return r;
}
__device__ __forceinline__ void ffma2(unsigned long long& acc, unsigned long long a, unsigned long long b){
    asm("fma.rn.f32x2 %0, %1, %2, %0;" : "+l"(acc) : "l"(a), "l"(b));
}
__device__ __forceinline__ float2 unpack2(unsigned long long v){
    float2 f;
    asm("mov.b64 {%0, %1}, %2;" : "=f"(f.x), "=f"(f.y) : "l"(v));
    return f;
}
// HW tanh (MUFU): 1 op, err ~2^-10.8.
__device__ __forceinline__ float tanh_a(float x){
    float r; asm("tanh.approx.f32 %0, %1;" : "=f"(r) : "f"(x)); return r;
}
// sigmoid with the 0.5x PRE-FOLDED into the weights: s = 0.5*tanh(g') + 0.5
__device__ __forceinline__ float sigmoid_pre(float xh){
    return fmaf(0.5f, tanh_a(xh), 0.5f);
}

// Architecture = R7 optimum (238us): TWO batches per warp, one warp per block,
// grid = B/2 = 1024 -> one wave; binding resource = SMSPs carrying 2 blocks.
// Changes vs R7:
//  (1) sigmoid-gate weights (rows i,f,o of W_hh/W_ih + bias) pre-scaled by 0.5
//      at register-load time -> per-step sigmoid = fma(0.5, tanh(g), 0.5):
//      6 fewer fp issues and a 4-cyc shorter serial chain per warp-step.
//  (2) clean anti-phase (no split-k this time): odd blocks burn a one-time
//      ~450-cyc dependent MUFU chain (result * 0.0f -> exact no-op) so
//      co-SMSP warp pairs alternate MAC phase vs MUFU/LSU tail phase.
__global__ void __launch_bounds__(32, 8) lstm_r13(
    const float* __restrict__ x,
    const float* __restrict__ W_ih,
    const float* __restrict__ W_hh,
    const float* __restrict__ b_ih,
    const float* __restrict__ b_hh,
    const float* __restrict__ W_fc,
    const float* __restrict__ b_fc,
    float* __restrict__ out,
    int B)
{
    const int lane = threadIdx.x;
    const int b0 = blockIdx.x * 2;
    const int b1 = b0 + 1;
    const bool has1 = (b1 < B);
    const int b1m = has1 ? b1 : b0;

    __shared__ __align__(16) float hs[2][32][36];
    __shared__ float wfcs[32];

    // ---- preload shared weights into registers; sigmoid rows pre-scaled ----
    unsigned long long w2[4][16];   // 4 gate rows x 16 packed k-pairs = 128 regs
    unsigned long long wx2[4];
    float bias[4];
#pragma unroll
    for (int r = 0; r < 4; r++){
        const float s = (r == 2) ? 1.0f : 0.5f;   // gate order i,f,g,o: tanh row r=2
        const int row = r * 32 + lane;
        const float4* wr = reinterpret_cast<const float4*>(W_hh) + row * 8;
#pragma unroll
        for (int q = 0; q < 8; q++){
            float4 v = wr[q];
            w2[r][2*q]   = pack2(s * v.x, s * v.y);
            w2[r][2*q+1] = pack2(s * v.z, s * v.w);
        }
        wx2[r]  = pack2(s * W_ih[row*2 + 0], s * W_ih[row*2 + 1]);
        bias[r] = s * (b_ih[row] + b_hh[row]);
    }
    wfcs[lane] = W_fc[lane];
    const float bfc = b_fc[0];

    // ---- one-time anti-phase delay for odd blocks (~28 x lat16 MUFU) ----
    float c0 = 0.0f, c1 = 0.0f;
    if (blockIdx.x & 1){
        float d = bias[0] + 1.0f;
#pragma unroll
        for (int i = 0; i < 28; i++)
            d = tanh_a(d + 0.7f);
        c0 = d * 0.0f;   // d finite -> exactly 0.0f; keeps the chain live
    }

    hs[0][31][lane] = 0.0f;   // h_{-1} = 0 (read by step 0)
    hs[1][31][lane] = 0.0f;
    __syncwarp();

    const float2* xr0 = reinterpret_cast<const float2*>(x) + (size_t)b0  * T_STEPS;
    const float2* xr1 = reinterpret_cast<const float2*>(x) + (size_t)b1m * T_STEPS;
    float2 xv0 = xr0[0];
    float2 xv1 = xr1[0];

    for (int tb = 0; tb < T_STEPS / 32; tb++){
#pragma unroll 1
        for (int ts = 0; ts < 32; ts++){
            const int t = (tb << 5) + ts;
            const int tn = (t + 1 < T_STEPS) ? (t + 1) : t;
            float2 xn0 = xr0[tn];           // prefetch next inputs
            float2 xn1 = xr1[tn];

            const int rp = (ts + 31) & 31;  // row holding h_{t-1}
            const ulonglong2* hp0 = reinterpret_cast<const ulonglong2*>(&hs[0][rp][0]);
            const ulonglong2* hp1 = reinterpret_cast<const ulonglong2*>(&hs[1][rp][0]);

            // init accumulators: lo = bias + x0*w0, hi = x1*w1 (scaled rows)
            unsigned long long xp0 = pack2(xv0.x, xv0.y);
            unsigned long long xp1 = pack2(xv1.x, xv1.y);
            unsigned long long a00 = pack2(bias[0], 0.f), a01 = pack2(bias[1], 0.f);
            unsigned long long a02 = pack2(bias[2], 0.f), a03 = pack2(bias[3], 0.f);
            unsigned long long a10 = a00, a11 = a01, a12 = a02, a13 = a03;
            ffma2(a00, xp0, wx2[0]); ffma2(a01, xp0, wx2[1]);
            ffma2(a02, xp0, wx2[2]); ffma2(a03, xp0, wx2[3]);
            ffma2(a10, xp1, wx2[0]); ffma2(a11, xp1, wx2[1]);
            ffma2(a12, xp1, wx2[2]); ffma2(a13, xp1, wx2[3]);

            // MAC core: 128 packed FFMA2, 8 independent chains (R7 layout)
#pragma unroll
            for (int q = 0; q < 8; q++){
                ulonglong2 v0 = hp0[q];
                ulonglong2 v1 = hp1[q];
                ffma2(a00, v0.x, w2[0][2*q]);   ffma2(a01, v0.x, w2[1][2*q]);
                ffma2(a02, v0.x, w2[2][2*q]);   ffma2(a03, v0.x, w2[3][2*q]);
                ffma2(a10, v1.x, w2[0][2*q]);   ffma2(a11, v1.x, w2[1][2*q]);
                ffma2(a12, v1.x, w2[2][2*q]);   ffma2(a13, v1.x, w2[3][2*q]);
                ffma2(a00, v0.y, w2[0][2*q+1]); ffma2(a01, v0.y, w2[1][2*q+1]);
                ffma2(a02, v0.y, w2[2][2*q+1]); ffma2(a03, v0.y, w2[3][2*q+1]);
                ffma2(a10, v1.y, w2[0][2*q+1]); ffma2(a11, v1.y, w2[1][2*q+1]);
                ffma2(a12, v1.y, w2[2][2*q+1]); ffma2(a13, v1.y, w2[3][2*q+1]);
            }

            // gates, batch 0
            {
                float2 f0 = unpack2(a00), f1 = unpack2(a01);
                float2 f2 = unpack2(a02), f3 = unpack2(a03);
                const float ig = sigmoid_pre(f0.x + f0.y);
                const float fg = sigmoid_pre(f1.x + f1.y);
                const float gg = tanh_a    (f2.x + f2.y);
                const float og = sigmoid_pre(f3.x + f3.y);
                c0 = fmaf(fg, c0, ig * gg);
                hs[0][ts][lane] = og * tanh_a(c0);
            }
            // gates, batch 1
            {
                float2 f0 = unpack2(a10), f1 = unpack2(a11);
                float2 f2 = unpack2(a12), f3 = unpack2(a13);
                const float ig = sigmoid_pre(f0.x + f0.y);
                const float fg = sigmoid_pre(f1.x + f1.y);
                const float gg = tanh_a    (f2.x + f2.y);
                const float og = sigmoid_pre(f3.x + f3.y);
                c1 = fmaf(fg, c1, ig * gg);
                hs[1][ts][lane] = og * tanh_a(c1);
            }

            __syncwarp();   // publish h_t before next step reads it
            xv0 = xn0;
            xv1 = xn1;
        }

        // ---- deferred FC head for this 32-step chunk ----
        float p0 = 0.0f, p1 = 0.0f;
#pragma unroll
        for (int k = 0; k < 32; k++){
            const float w = wfcs[k];
            p0 = fmaf(hs[0][lane][k], w, p0);
            p1 = fmaf(hs[1][lane][k], w, p1);
        }
        const int to = (tb << 5) + lane;
        out[(size_t)b0 * T_STEPS + to] = p0 + bfc;
        if (has1) out[(size_t)b1 * T_STEPS + to] = p1 + bfc;
        __syncwarp();   // chunk rows may be overwritten next chunk
    }
}

extern "C" void kernel_launch(void* const* d_in, const int* in_sizes, int n_in,
                              void* d_out, int out_size)
{
    const float* x   = (const float*)d_in[0];
    const float* Wih = (const float*)d_in[1];
    const float* Whh = (const float*)d_in[2];
    const float* bih = (const float*)d_in[3];
    const float* bhh = (const float*)d_in[4];
    const float* Wfc = (const float*)d_in[5];
    const float* bfc = (const float*)d_in[6];
    float* out = (float*)d_out;

    const int B = out_size / T_STEPS;      // OUT=1 -> out_size = B*T
    const int grid = (B + 1) / 2;          // two batch elements per warp
    lstm_r13<<<grid, 32>>>(x, Wih, Whh, bih, bhh, Wfc, bfc, out, B);
}

// round 16
// speedup vs baseline: 1.1077x; 1.0106x over previous
#include <cuda_runtime.h>

#define T_STEPS 512

// ---- packed f32x2 helpers (sm_100+ PTX) ----
__device__ __forceinline__ unsigned long long pack2(float lo, float hi){
    unsigned long long r;
    asm("mov.b64 %0, {%1, %2};" : "=l"(r) : "f"(lo), "f"(hi));
    return r;
}
__device__ __forceinline__ void ffma2(unsigned long long& acc, unsigned long long a, unsigned long long b){
    asm("fma.rn.f32x2 %0, %1, %2, %0;" : "+l"(acc) : "l"(a), "l"(b));
}
__device__ __forceinline__ float2 unpack2(unsigned long long v){
    float2 f;
    asm("mov.b64 {%0, %1}, %2;" : "=f"(f.x), "=f"(f.y) : "l"(v));
    return f;
}
// HW tanh (MUFU): 1 op, err ~2^-10.8.
__device__ __forceinline__ float tanh_a(float x){
    float r; asm("tanh.approx.f32 %0, %1;" : "=f"(r) : "f"(x)); return r;
}
// sigmoid with the 0.5x PRE-FOLDED into the weights: s = 0.5*tanh(g') + 0.5
__device__ __forceinline__ float sigmoid_pre(float xh){
    return fmaf(0.5f, tanh_a(xh), 0.5f);
}

// Architecture = R7 optimum: TWO batches per warp, one warp per block,
// grid = B/2 = 1024 -> one wave, ~2 warps/SMSP.
// Changes vs the 238us baseline:
//  (1) NO per-step __syncwarp. The h slab round-trip is a same-warp,
//      non-divergent STS -> LDS: program order + the per-warp in-order LSU
//      guarantee the store wavefront commits before the next step's load
//      wavefront reads it (and per-thread alias keeps ptxas from reordering).
//      Deletes ~23 serial cyc/step AND unfences cross-step scheduling.
//  (2) #pragma unroll 2 on the step loop so ptxas can slide step t+1's
//      x-loads / address math / acc inits under step t's MUFU tail.
//  (3) sigmoid 0.5x pre-fold kept (shorter gate chain, fewer issues).
__global__ void __launch_bounds__(32, 8) lstm_r15(
    const float* __restrict__ x,
    const float* __restrict__ W_ih,
    const float* __restrict__ W_hh,
    const float* __restrict__ b_ih,
    const float* __restrict__ b_hh,
    const float* __restrict__ W_fc,
    const float* __restrict__ b_fc,
    float* __restrict__ out,
    int B)
{
    const int lane = threadIdx.x;
    const int b0 = blockIdx.x * 2;
    const int b1 = b0 + 1;
    const bool has1 = (b1 < B);
    const int b1m = has1 ? b1 : b0;

    __shared__ __align__(16) float hs[2][32][36];
    __shared__ float wfcs[32];

    // ---- preload shared weights into registers; sigmoid rows pre-scaled ----
    unsigned long long w2[4][16];   // 4 gate rows x 16 packed k-pairs = 128 regs
    unsigned long long wx2[4];
    float bias[4];
#pragma unroll
    for (int r = 0; r < 4; r++){
        const float s = (r == 2) ? 1.0f : 0.5f;   // gate order i,f,g,o
        const int row = r * 32 + lane;
        const float4* wr = reinterpret_cast<const float4*>(W_hh) + row * 8;
#pragma unroll
        for (int q = 0; q < 8; q++){
            float4 v = wr[q];
            w2[r][2*q]   = pack2(s * v.x, s * v.y);
            w2[r][2*q+1] = pack2(s * v.z, s * v.w);
        }
        wx2[r]  = pack2(s * W_ih[row*2 + 0], s * W_ih[row*2 + 1]);
        bias[r] = s * (b_ih[row] + b_hh[row]);
    }
    wfcs[lane] = W_fc[lane];
    const float bfc = b_fc[0];

    float c0 = 0.0f, c1 = 0.0f;
    hs[0][31][lane] = 0.0f;   // h_{-1} = 0 (read by step 0)
    hs[1][31][lane] = 0.0f;
    __syncwarp();

    const float2* xr0 = reinterpret_cast<const float2*>(x) + (size_t)b0  * T_STEPS;
    const float2* xr1 = reinterpret_cast<const float2*>(x) + (size_t)b1m * T_STEPS;
    float2 xv0 = xr0[0];
    float2 xv1 = xr1[0];

    for (int tb = 0; tb < T_STEPS / 32; tb++){
#pragma unroll 2
        for (int ts = 0; ts < 32; ts++){
            const int t = (tb << 5) + ts;
            const int tn = (t + 1 < T_STEPS) ? (t + 1) : t;
            float2 xn0 = xr0[tn];           // prefetch next inputs
            float2 xn1 = xr1[tn];

            const int rp = (ts + 31) & 31;  // row holding h_{t-1}
            const ulonglong2* hp0 = reinterpret_cast<const ulonglong2*>(&hs[0][rp][0]);
            const ulonglong2* hp1 = reinterpret_cast<const ulonglong2*>(&hs[1][rp][0]);

            // init accumulators: lo = bias + x0*w0, hi = x1*w1 (scaled rows)
            unsigned long long xp0 = pack2(xv0.x, xv0.y);
            unsigned long long xp1 = pack2(xv1.x, xv1.y);
            unsigned long long a00 = pack2(bias[0], 0.f), a01 = pack2(bias[1], 0.f);
            unsigned long long a02 = pack2(bias[2], 0.f), a03 = pack2(bias[3], 0.f);
            unsigned long long a10 = a00, a11 = a01, a12 = a02, a13 = a03;
            ffma2(a00, xp0, wx2[0]); ffma2(a01, xp0, wx2[1]);
            ffma2(a02, xp0, wx2[2]); ffma2(a03, xp0, wx2[3]);
            ffma2(a10, xp1, wx2[0]); ffma2(a11, xp1, wx2[1]);
            ffma2(a12, xp1, wx2[2]); ffma2(a13, xp1, wx2[3]);

            // MAC core: 128 packed FFMA2, 8 independent chains
#pragma unroll
            for (int q = 0; q < 8; q++){
                ulonglong2 v0 = hp0[q];
                ulonglong2 v1 = hp1[q];
                ffma2(a00, v0.x, w2[0][2*q]);   ffma2(a01, v0.x, w2[1][2*q]);
                ffma2(a02, v0.x, w2[2][2*q]);   ffma2(a03, v0.x, w2[3][2*q]);
                ffma2(a10, v1.x, w2[0][2*q]);   ffma2(a11, v1.x, w2[1][2*q]);
                ffma2(a12, v1.x, w2[2][2*q]);   ffma2(a13, v1.x, w2[3][2*q]);
                ffma2(a00, v0.y, w2[0][2*q+1]); ffma2(a01, v0.y, w2[1][2*q+1]);
                ffma2(a02, v0.y, w2[2][2*q+1]); ffma2(a03, v0.y, w2[3][2*q+1]);
                ffma2(a10, v1.y, w2[0][2*q+1]); ffma2(a11, v1.y, w2[1][2*q+1]);
                ffma2(a12, v1.y, w2[2][2*q+1]); ffma2(a13, v1.y, w2[3][2*q+1]);
            }

            // gates, batch 0
            {
                float2 f0 = unpack2(a00), f1 = unpack2(a01);
                float2 f2 = unpack2(a02), f3 = unpack2(a03);
                const float ig = sigmoid_pre(f0.x + f0.y);
                const float fg = sigmoid_pre(f1.x + f1.y);
                const float gg = tanh_a    (f2.x + f2.y);
                const float og = sigmoid_pre(f3.x + f3.y);
                c0 = fmaf(fg, c0, ig * gg);
                hs[0][ts][lane] = og * tanh_a(c0);
            }
            // gates, batch 1
            {
                float2 f0 = unpack2(a10), f1 = unpack2(a11);
                float2 f2 = unpack2(a12), f3 = unpack2(a13);
                const float ig = sigmoid_pre(f0.x + f0.y);
                const float fg = sigmoid_pre(f1.x + f1.y);
                const float gg = tanh_a    (f2.x + f2.y);
                const float og = sigmoid_pre(f3.x + f3.y);
                c1 = fmaf(fg, c1, ig * gg);
                hs[1][ts][lane] = og * tanh_a(c1);
            }

            // NO __syncwarp: same-warp in-order STS->LDS through the slab;
            // next iteration's LDS of row ts is ordered after this STS by the
            // per-warp LSU and by per-thread alias analysis in ptxas.
            xv0 = xn0;
            xv1 = xn1;
        }

        // ---- deferred FC head for this 32-step chunk ----
        // cross-lane reads (hs[*][lane][k]) -> one real syncwarp per 32 steps
        __syncwarp();
        float p0 = 0.0f, p1 = 0.0f;
#pragma unroll
        for (int k = 0; k < 32; k++){
            const float w = wfcs[k];
            p0 = fmaf(hs[0][lane][k], w, p0);
            p1 = fmaf(hs[1][lane][k], w, p1);
        }
        const int to = (tb << 5) + lane;
        out[(size_t)b0 * T_STEPS + to] = p0 + bfc;
        if (has1) out[(size_t)b1 * T_STEPS + to] = p1 + bfc;
        __syncwarp();   // chunk rows may be overwritten next chunk
    }
}

extern "C" void kernel_launch(void* const* d_in, const int* in_sizes, int n_in,
                              void* d_out, int out_size)
{
    const float* x   = (const float*)d_in[0];
    const float* Wih = (const float*)d_in[1];
    const float* Whh = (const float*)d_in[2];
    const float* bih = (const float*)d_in[3];
    const float* bhh = (const float*)d_in[4];
    const float* Wfc = (const float*)d_in[5];
    const float* bfc = (const float*)d_in[6];
    float* out = (float*)d_out;

    const int B = out_size / T_STEPS;      // OUT=1 -> out_size = B*T
    const int grid = (B + 1) / 2;          // two batch elements per warp
    lstm_r15<<<grid, 32>>>(x, Wih, Whh, bih, bhh, Wfc, bfc, out, B);
}